// round 12
// baseline (speedup 1.0000x reference)
#include <cuda_runtime.h>
#include <cstdint>

#define BB   8
#define SS   128
#define DD   300
#define EE   50
#define DEPC 50
#define RROWS 8
#define NTHR 512

__device__ float g_M  [BB * SS * SS];
__device__ float g_Wt [DD * DD];        // Wt[d][j]  = Ww[j][d]
__device__ float g_W1t[DD * 100];       // W1t[d][o] = W1w[o>>1][(o&1)*300 + d]
__device__ float g_Pa [BB * SS * DEPC];
__device__ float g_Pb [BB * SS * DEPC];

using ull = unsigned long long;

__device__ __forceinline__ ull pk2(float x, float y) {
    ull r; asm("mov.b64 %0, {%1,%2};" : "=l"(r) : "f"(x), "f"(y)); return r;
}
__device__ __forceinline__ ull f2fma(ull a, ull b, ull c) {
    ull d; asm("fma.rn.f32x2 %0, %1, %2, %3;" : "=l"(d) : "l"(a), "l"(b), "l"(c)); return d;
}
__device__ __forceinline__ ull f2add(ull a, ull b) {
    ull d; asm("add.rn.f32x2 %0, %1, %2;" : "=l"(d) : "l"(a), "l"(b)); return d;
}
__device__ __forceinline__ void upk2(ull v, float& x, float& y) {
    asm("mov.b64 {%0,%1}, %2;" : "=f"(x), "=f"(y) : "l"(v));
}
__device__ __forceinline__ void fma4(ull* a, float wv, ull r0, ull r1, ull r2, ull r3) {
    ull w = pk2(wv, wv);
    a[0] = f2fma(w, r0, a[0]); a[1] = f2fma(w, r1, a[1]);
    a[2] = f2fma(w, r2, a[2]); a[3] = f2fma(w, r3, a[3]);
}

// =======================================================================
// k_prep_w: transpose W -> g_Wt, scatter W1 -> g_W1t.
// k_pref_x: warm L2 for x.  (Two launches so ncu -s5-c1 lands on k_compute.)
// =======================================================================
__global__ void k_prep_w(const float* __restrict__ Ww, const float* __restrict__ W1w) {
    const int bid = blockIdx.x;
    const int tid = threadIdx.x;
    if (bid < 100) {                       // W 32x32 tile transpose
        __shared__ float tile[32][33];
        const int jt = (bid / 10) * 32, dt = (bid % 10) * 32;
        const int tx = tid & 31, ty = tid >> 5;
#pragma unroll
        for (int yy = ty; yy < 32; yy += 8) {
            int j = jt + yy, d = dt + tx;
            tile[yy][tx] = (j < DD && d < DD) ? Ww[j * DD + d] : 0.f;
        }
        __syncthreads();
#pragma unroll
        for (int yy = ty; yy < 32; yy += 8) {
            int d = dt + yy, j = jt + tx;
            if (d < DD && j < DD) g_Wt[d * DD + j] = tile[tx][yy];
        }
    } else {                               // W1t scatter (30000 elements)
        for (int idx = (bid - 100) * 256 + tid; idx < 100 * DD; idx += 20 * 256) {
            int e = idx / 600, c = idx - e * 600;
            int d = c % DD, half = c / DD;
            g_W1t[d * 100 + 2 * e + half] = W1w[idx];
        }
    }
}
__global__ void k_pref_x(const float* __restrict__ x) {
    int i = blockIdx.x * blockDim.x + threadIdx.x;
    float v = 0.f;
    if (i < 38400) v = x[i * 8];
    asm volatile("" :: "f"(v));
}

// =======================================================================
// k_reduce: M[b,s,t] = (1/E)(sum_e wps[b,s,t,e] + sum_e sl[b,e,s,t])
// =======================================================================
#define RED_SMEM_FLOATS (2 * 128 * EE + 256)
#define RED_SMEM_BYTES  (RED_SMEM_FLOATS * 4)    // 52224 B

__global__ __launch_bounds__(256, 3) void k_reduce(const float* __restrict__ wps,
                                                   const float* __restrict__ sl) {
    extern __shared__ float rsm[];
    float* W  = rsm;
    float* SL = rsm + 2 * 128 * EE;
    const int tid = threadIdx.x;
    const int blk = blockIdx.x;
    const int b   = blk >> 6;
    const int s0  = (blk & 63) * 2;

    const float4* src = reinterpret_cast<const float4*>(wps) + (size_t)(b * SS + s0) * 1600;
    float4* W4 = reinterpret_cast<float4*>(W);
    float4 v[12];
#pragma unroll
    for (int k = 0; k < 12; k++) v[k] = src[tid + 256 * k];
    float4 v12;
    const bool tail = tid < 128;
    if (tail) v12 = src[tid + 3072];

    float slacc;
    {
        const float* sp_ = sl + (size_t)b * EE * SS * SS + (s0 + (tid >> 7)) * SS + (tid & 127);
        float p[5] = {0.f, 0.f, 0.f, 0.f, 0.f};
#pragma unroll
        for (int e = 0; e < EE; e++) p[e % 5] += sp_[(size_t)e * SS * SS];
        slacc = (p[0] + p[1]) + (p[2] + p[3]) + p[4];
    }

#pragma unroll
    for (int k = 0; k < 12; k++) W4[tid + 256 * k] = v[k];
    if (tail) W4[tid + 3072] = v12;
    SL[tid] = slacc;
    __syncthreads();

    float s1 = 0.f;
    const float* wr = W + tid * EE;
#pragma unroll
    for (int i = 0; i < EE; i++) s1 += wr[i];
    g_M[(size_t)(b * SS + s0 + (tid >> 7)) * SS + (tid & 127)] = (s1 + SL[tid]) * (1.0f / EE);
}

// =======================================================================
// k_compute: per (b, 8-row group). Coalesced LDG.128 weights from the
// transposed copies; batch loops now unrolled so ptxas pipelines LDGs
// across batches (was unroll-1 -> one exposed L2 latency per batch).
// =======================================================================
#define OFF_MS    0        // 1024 f : Ms[r*128+t]
#define OFF_AX    1024     // 2400 f : AxP f2 [d*4+rp]
#define OFF_NS    3424     // 2400 f : g/node f2 [j*4+rp]
#define OFF_GH    5824     // 12000 f: 6000 ull combine scratch
#define OFF_RED   17824    // 128
#define OFF_MEAN  17952    // 8
#define OFF_INVD  17960    // 8
#define SMEM_FLOATS 17968
#define SMEM_BYTES  (SMEM_FLOATS * 4)

__global__ __launch_bounds__(NTHR, 1) void k_compute(
    const float* __restrict__ x,   const float* __restrict__ Wb,
    const float* __restrict__ lna, const float* __restrict__ lnb,
    float* __restrict__ node_out)
{
    extern __shared__ float sm[];
    float*  Ms    = sm + OFF_MS;
    float2* AxP   = reinterpret_cast<float2*>(sm + OFF_AX);
    float2* NsP   = reinterpret_cast<float2*>(sm + OFF_NS);
    ull*    GH    = reinterpret_cast<ull*>(sm + OFF_GH);
    float*  red   = sm + OFF_RED;
    float*  means = sm + OFF_MEAN;
    float*  invd  = sm + OFF_INVD;

    const int tid = threadIdx.x;
    const int b   = blockIdx.x >> 4;
    const int s0  = (blockIdx.x & 15) * RROWS;

    if (tid < 256)
        reinterpret_cast<float4*>(Ms)[tid] =
            reinterpret_cast<const float4*>(g_M + (size_t)(b * SS + s0) * SS)[tid];
    __syncthreads();

    // ========== Phase 1: Ax[r][d] = sum_t M[r][t] x[t][d] ==========
    ull acc1[16];
    if (tid < 300) {
        const int tseg = tid / 75, dq = tid % 75, d0 = dq * 4;
        const float* xb = x + (size_t)b * SS * DD + d0;
        const int t0 = tseg * 32;
#pragma unroll
        for (int k = 0; k < 16; k++) acc1[k] = 0;
#pragma unroll 2
        for (int tb = 0; tb < 4; tb++) {
            float4 xq[8];
#pragma unroll
            for (int u = 0; u < 8; u++)
                xq[u] = *reinterpret_cast<const float4*>(xb + (size_t)(t0 + tb * 8 + u) * DD);
#pragma unroll
            for (int u = 0; u < 8; u++) {
                const int t = t0 + tb * 8 + u;
                ull xlo = pk2(xq[u].x, xq[u].y), xhi = pk2(xq[u].z, xq[u].w);
#pragma unroll
                for (int r = 0; r < 8; r++) {
                    ull mm = pk2(Ms[r * SS + t], Ms[r * SS + t]);
                    acc1[r * 2]     = f2fma(mm, xlo, acc1[r * 2]);
                    acc1[r * 2 + 1] = f2fma(mm, xhi, acc1[r * 2 + 1]);
                }
            }
        }
        if (tseg) {
            ull* g = GH + (size_t)((tseg - 1) * 75 + dq) * 16;
#pragma unroll
            for (int k = 0; k < 16; k++) g[k] = acc1[k];
        }
    }
    __syncthreads();
    if (tid < 75) {
#pragma unroll
        for (int s = 0; s < 3; s++)
#pragma unroll
            for (int k = 0; k < 16; k++) acc1[k] = f2add(acc1[k], GH[(size_t)(s * 75 + tid) * 16 + k]);
        float v[8][4];
#pragma unroll
        for (int r = 0; r < 8; r++) {
            upk2(acc1[r * 2],     v[r][0], v[r][1]);
            upk2(acc1[r * 2 + 1], v[r][2], v[r][3]);
        }
        const int d0 = tid * 4;
#pragma unroll
        for (int dd = 0; dd < 4; dd++)
#pragma unroll
            for (int rp = 0; rp < 4; rp++)
                AxP[(d0 + dd) * 4 + rp] = make_float2(v[2 * rp][dd], v[2 * rp + 1][dd]);
    }
    __syncthreads();

    // ========== Phase 2: g = Ax @ W^T + b ==========
    ull acc2[16];
#pragma unroll
    for (int k = 0; k < 16; k++) acc2[k] = 0;
    if (tid < 450) {
        const int seg = tid / 75, jg = tid % 75;
        const int d0 = seg * 50, j0 = jg * 4;
        const float* wtb = g_Wt + j0;
#pragma unroll 2
        for (int pb = 0; pb < 5; pb++) {
            float4 wq[10];
#pragma unroll
            for (int u = 0; u < 5; u++) {
                int d = d0 + (pb * 5 + u) * 2;
                wq[2 * u]     = *reinterpret_cast<const float4*>(wtb + (size_t)d * DD);
                wq[2 * u + 1] = *reinterpret_cast<const float4*>(wtb + (size_t)(d + 1) * DD);
            }
#pragma unroll
            for (int u = 0; u < 5; u++) {
                int d = d0 + (pb * 5 + u) * 2;
                const ulonglong2* ap = reinterpret_cast<const ulonglong2*>(&AxP[d * 4]);
                ulonglong2 a0 = ap[0], a1 = ap[1], b0 = ap[2], b1 = ap[3];
                float4 wa = wq[2 * u], wv = wq[2 * u + 1];
                fma4(acc2 + 0,  wa.x, a0.x, a0.y, a1.x, a1.y);
                fma4(acc2 + 4,  wa.y, a0.x, a0.y, a1.x, a1.y);
                fma4(acc2 + 8,  wa.z, a0.x, a0.y, a1.x, a1.y);
                fma4(acc2 + 12, wa.w, a0.x, a0.y, a1.x, a1.y);
                fma4(acc2 + 0,  wv.x, b0.x, b0.y, b1.x, b1.y);
                fma4(acc2 + 4,  wv.y, b0.x, b0.y, b1.x, b1.y);
                fma4(acc2 + 8,  wv.z, b0.x, b0.y, b1.x, b1.y);
                fma4(acc2 + 12, wv.w, b0.x, b0.y, b1.x, b1.y);
            }
        }
        if (seg) {
            ull* g = GH + (size_t)((seg - 1) * 75 + jg) * 16;
#pragma unroll
            for (int k = 0; k < 16; k++) g[k] = acc2[k];
        }
    }
    __syncthreads();
    if (tid < 75) {
#pragma unroll
        for (int s = 0; s < 5; s++)
#pragma unroll
            for (int k = 0; k < 16; k++) acc2[k] = f2add(acc2[k], GH[(size_t)(s * 75 + tid) * 16 + k]);
#pragma unroll
        for (int jj = 0; jj < 4; jj++) {
            int j = tid * 4 + jj;
            ull b2 = pk2(Wb[j], Wb[j]);
#pragma unroll
            for (int rp = 0; rp < 4; rp++) {
                ull vv = f2add(acc2[jj * 4 + rp], b2);
                *reinterpret_cast<ull*>(&NsP[j * 4 + rp]) = vv;
            }
        }
    }
    __syncthreads();

    // ========== Phase 3: LayerNorm (ddof=1) + relu ==========
    const int lane = tid & 31, warp = tid >> 5;
    float gj[RROWS];
    const bool jown = (tid < DD);
    if (jown) {
        const ulonglong2* nv = reinterpret_cast<const ulonglong2*>(NsP + tid * 4);
        ulonglong2 a = nv[0], bq = nv[1];
        upk2(a.x,  gj[0], gj[1]); upk2(a.y,  gj[2], gj[3]);
        upk2(bq.x, gj[4], gj[5]); upk2(bq.y, gj[6], gj[7]);
    }
    {
        float s[RROWS];
#pragma unroll
        for (int r = 0; r < RROWS; r++) s[r] = jown ? gj[r] : 0.f;
#pragma unroll
        for (int off = 16; off; off >>= 1)
#pragma unroll
            for (int r = 0; r < RROWS; r++) s[r] += __shfl_down_sync(0xffffffffu, s[r], off);
        if (lane == 0)
#pragma unroll
            for (int r = 0; r < RROWS; r++) red[warp * RROWS + r] = s[r];
    }
    __syncthreads();
    if (tid < RROWS) {
        float s = 0.f;
#pragma unroll
        for (int w = 0; w < NTHR / 32; w++) s += red[w * RROWS + tid];
        means[tid] = s * (1.0f / DD);
    }
    __syncthreads();
    {
        float s[RROWS];
#pragma unroll
        for (int r = 0; r < RROWS; r++) {
            float dv = jown ? (gj[r] - means[r]) : 0.f;
            s[r] = dv * dv;
        }
#pragma unroll
        for (int off = 16; off; off >>= 1)
#pragma unroll
            for (int r = 0; r < RROWS; r++) s[r] += __shfl_down_sync(0xffffffffu, s[r], off);
        if (lane == 0)
#pragma unroll
            for (int r = 0; r < RROWS; r++) red[warp * RROWS + r] = s[r];
    }
    __syncthreads();
    if (tid < RROWS) {
        float s = 0.f;
#pragma unroll
        for (int w = 0; w < NTHR / 32; w++) s += red[w * RROWS + tid];
        float stdv = sqrtf(s * (1.0f / (DD - 1)));   // ddof = 1
        invd[tid] = 1.0f / (stdv + 1e-6f);
    }
    __syncthreads();

    if (jown) {
        float a = lna[tid], bb2 = lnb[tid];
        float nv[RROWS];
#pragma unroll
        for (int r = 0; r < RROWS; r++) {
            float v = a * (gj[r] - means[r]) * invd[r] + bb2;
            nv[r] = v > 0.f ? v : 0.f;
            node_out[(size_t)(b * SS + s0 + r) * DD + tid] = nv[r];
        }
#pragma unroll
        for (int rp = 0; rp < 4; rp++)
            NsP[tid * 4 + rp] = make_float2(nv[2 * rp], nv[2 * rp + 1]);
    }
    __syncthreads();

    // ========== Phase 4: P = node @ W1^T (o<100 interleaved pa/pb) ==========
    ull acc4[16];
#pragma unroll
    for (int k = 0; k < 16; k++) acc4[k] = 0;
    if (tid < 250) {
        const int seg = tid / 25, og = tid % 25;
        const int d0 = seg * 30, o0 = og * 4;
        const float* wtb = g_W1t + o0;
#pragma unroll
        for (int pb = 0; pb < 3; pb++) {
            float4 wq[10];
#pragma unroll
            for (int u = 0; u < 5; u++) {
                int d = d0 + (pb * 5 + u) * 2;
                wq[2 * u]     = *reinterpret_cast<const float4*>(wtb + (size_t)d * 100);
                wq[2 * u + 1] = *reinterpret_cast<const float4*>(wtb + (size_t)(d + 1) * 100);
            }
#pragma unroll
            for (int u = 0; u < 5; u++) {
                int d = d0 + (pb * 5 + u) * 2;
                const ulonglong2* np = reinterpret_cast<const ulonglong2*>(&NsP[d * 4]);
                ulonglong2 a0 = np[0], a1 = np[1], b0 = np[2], b1 = np[3];
                float4 wa = wq[2 * u], wv = wq[2 * u + 1];
                fma4(acc4 + 0,  wa.x, a0.x, a0.y, a1.x, a1.y);
                fma4(acc4 + 4,  wa.y, a0.x, a0.y, a1.x, a1.y);
                fma4(acc4 + 8,  wa.z, a0.x, a0.y, a1.x, a1.y);
                fma4(acc4 + 12, wa.w, a0.x, a0.y, a1.x, a1.y);
                fma4(acc4 + 0,  wv.x, b0.x, b0.y, b1.x, b1.y);
                fma4(acc4 + 4,  wv.y, b0.x, b0.y, b1.x, b1.y);
                fma4(acc4 + 8,  wv.z, b0.x, b0.y, b1.x, b1.y);
                fma4(acc4 + 12, wv.w, b0.x, b0.y, b1.x, b1.y);
            }
        }
        if (seg) {
            ull* g = GH + (size_t)((seg - 1) * 25 + og) * 16;
#pragma unroll
            for (int k = 0; k < 16; k++) g[k] = acc4[k];
        }
    }
    __syncthreads();
    if (tid < 25) {
#pragma unroll
        for (int s = 0; s < 9; s++)
#pragma unroll
            for (int k = 0; k < 16; k++) acc4[k] = f2add(acc4[k], GH[(size_t)(s * 25 + tid) * 16 + k]);
#pragma unroll
        for (int jj = 0; jj < 4; jj++) {
            int o = tid * 4 + jj, e = o >> 1;
            float* dst = ((o & 1) ? g_Pb : g_Pa) + (size_t)(b * SS + s0) * DEPC + e;
#pragma unroll
            for (int rp = 0; rp < 4; rp++) {
                float f0, f1;
                upk2(acc4[jj * 4 + rp], f0, f1);
                dst[(2 * rp) * DEPC]     = f0;
                dst[(2 * rp + 1) * DEPC] = f1;
            }
        }
    }
}

// =======================================================================
// k_edge: edge[b,i,j,e] = pa[b,j,e] + pb[b,i,e] + W1_b[e]
// 800 threads (25 full warps): e2 = tid%25, j0 = tid/25 in [0,32);
// 8 STG.64 per thread; pa cached in regs across the 2 rows.
// =======================================================================
__global__ __launch_bounds__(800) void k_edge(const float* __restrict__ W1b,
                                              float* __restrict__ edge) {
    const int bi0 = blockIdx.x * 2;
    const int b   = bi0 >> 7;
    const int tid = threadIdx.x;
    const int e2  = tid % 25;
    const int j0  = tid / 25;          // 0..31

    float2 w = reinterpret_cast<const float2*>(W1b)[e2];
    const ull* pa = reinterpret_cast<const ull*>(g_Pa + (size_t)b * SS * DEPC);
    ull pav[4];
#pragma unroll
    for (int k = 0; k < 4; k++) pav[k] = pa[(j0 + 32 * k) * 25 + e2];

#pragma unroll
    for (int r = 0; r < 2; r++) {
        int bi = bi0 + r;
        float2 pv = reinterpret_cast<const float2*>(g_Pb + (size_t)bi * DEPC)[e2];
        ull pr = pk2(pv.x + w.x, pv.y + w.y);
        ull* out = reinterpret_cast<ull*>(edge + (size_t)bi * SS * DEPC);
#pragma unroll
        for (int k = 0; k < 4; k++) out[(j0 + 32 * k) * 25 + e2] = f2add(pav[k], pr);
    }
}

// =======================================================================
extern "C" void kernel_launch(void* const* d_in, const int* in_sizes, int n_in,
                              void* d_out, int out_size) {
    const float* wps = (const float*)d_in[0];
    /* d_in[1] = weight_adj (int64) — unused */
    const float* x   = (const float*)d_in[2];
    const float* sl  = (const float*)d_in[3];
    const float* Ww  = (const float*)d_in[4];
    const float* Wb  = (const float*)d_in[5];
    const float* lna = (const float*)d_in[6];
    const float* lnb = (const float*)d_in[7];
    const float* W1w = (const float*)d_in[8];
    const float* W1b = (const float*)d_in[9];

    float* out  = (float*)d_out;
    float* node = out;
    float* edge = out + BB * SS * DD;

    cudaFuncSetAttribute((const void*)k_reduce,
                         cudaFuncAttributeMaxDynamicSharedMemorySize, RED_SMEM_BYTES);
    cudaFuncSetAttribute((const void*)k_compute,
                         cudaFuncAttributeMaxDynamicSharedMemorySize, SMEM_BYTES);

    k_prep_w <<<120, 256>>>(Ww, W1w);
    k_pref_x <<<150, 256>>>(x);
    k_reduce <<<BB * SS / 2, 256, RED_SMEM_BYTES>>>(wps, sl);
    k_compute<<<BB * (SS / RROWS), NTHR, SMEM_BYTES>>>(x, Wb, lna, lnb, node);
    k_edge   <<<BB * SS / 2, 800>>>(W1b, edge);
}

// round 15
// speedup vs baseline: 1.1073x; 1.1073x over previous
#include <cuda_runtime.h>
#include <cstdint>

#define BB   8
#define SS   128
#define DD   300
#define EE   50
#define DEPC 50
#define RROWS 4
#define NTHR 256

__device__ float g_M  [BB * SS * SS];
__device__ float g_Wt [DD * DD];        // Wt[d][j]  = Ww[j][d]
__device__ float g_W1t[DD * 100];       // W1t[d][o] = W1w[o>>1][(o&1)*300 + d]
__device__ float g_Pa [BB * SS * DEPC];
__device__ float g_Pb [BB * SS * DEPC];

using ull = unsigned long long;

__device__ __forceinline__ ull pk2(float x, float y) {
    ull r; asm("mov.b64 %0, {%1,%2};" : "=l"(r) : "f"(x), "f"(y)); return r;
}
__device__ __forceinline__ ull f2fma(ull a, ull b, ull c) {
    ull d; asm("fma.rn.f32x2 %0, %1, %2, %3;" : "=l"(d) : "l"(a), "l"(b), "l"(c)); return d;
}
__device__ __forceinline__ ull f2add(ull a, ull b) {
    ull d; asm("add.rn.f32x2 %0, %1, %2;" : "=l"(d) : "l"(a), "l"(b)); return d;
}
__device__ __forceinline__ void upk2(ull v, float& x, float& y) {
    asm("mov.b64 {%0,%1}, %2;" : "=f"(x), "=f"(y) : "l"(v));
}
__device__ __forceinline__ void fma2p(ull* a, float w, ull r0, ull r1) {
    ull ww = pk2(w, w);
    a[0] = f2fma(ww, r0, a[0]); a[1] = f2fma(ww, r1, a[1]);
}

// =======================================================================
// k_prep_w / k_pref_x  (launch order keeps ncu -s5-c1 on k_compute)
// =======================================================================
__global__ void k_prep_w(const float* __restrict__ Ww, const float* __restrict__ W1w) {
    const int bid = blockIdx.x;
    const int tid = threadIdx.x;
    if (bid < 100) {
        __shared__ float tile[32][33];
        const int jt = (bid / 10) * 32, dt = (bid % 10) * 32;
        const int tx = tid & 31, ty = tid >> 5;
#pragma unroll
        for (int yy = ty; yy < 32; yy += 8) {
            int j = jt + yy, d = dt + tx;
            tile[yy][tx] = (j < DD && d < DD) ? Ww[j * DD + d] : 0.f;
        }
        __syncthreads();
#pragma unroll
        for (int yy = ty; yy < 32; yy += 8) {
            int d = dt + yy, j = jt + tx;
            if (d < DD && j < DD) g_Wt[d * DD + j] = tile[tx][yy];
        }
    } else {
        for (int idx = (bid - 100) * 256 + tid; idx < 100 * DD; idx += 20 * 256) {
            int e = idx / 600, c = idx - e * 600;
            int d = c % DD, half = c / DD;
            g_W1t[d * 100 + 2 * e + half] = W1w[idx];
        }
    }
}
__global__ void k_pref_x(const float* __restrict__ x) {
    int i = blockIdx.x * blockDim.x + threadIdx.x;
    float v = 0.f;
    if (i < 38400) v = x[i * 8];
    asm volatile("" :: "f"(v));
}

// =======================================================================
// k_reduce (unchanged)
// =======================================================================
#define RED_SMEM_FLOATS (2 * 128 * EE + 256)
#define RED_SMEM_BYTES  (RED_SMEM_FLOATS * 4)

__global__ __launch_bounds__(256, 3) void k_reduce(const float* __restrict__ wps,
                                                   const float* __restrict__ sl) {
    extern __shared__ float rsm[];
    float* W  = rsm;
    float* SL = rsm + 2 * 128 * EE;
    const int tid = threadIdx.x;
    const int blk = blockIdx.x;
    const int b   = blk >> 6;
    const int s0  = (blk & 63) * 2;

    const float4* src = reinterpret_cast<const float4*>(wps) + (size_t)(b * SS + s0) * 1600;
    float4* W4 = reinterpret_cast<float4*>(W);
    float4 v[12];
#pragma unroll
    for (int k = 0; k < 12; k++) v[k] = src[tid + 256 * k];
    float4 v12;
    const bool tail = tid < 128;
    if (tail) v12 = src[tid + 3072];

    float slacc;
    {
        const float* sp_ = sl + (size_t)b * EE * SS * SS + (s0 + (tid >> 7)) * SS + (tid & 127);
        float p[5] = {0.f, 0.f, 0.f, 0.f, 0.f};
#pragma unroll
        for (int e = 0; e < EE; e++) p[e % 5] += sp_[(size_t)e * SS * SS];
        slacc = (p[0] + p[1]) + (p[2] + p[3]) + p[4];
    }

#pragma unroll
    for (int k = 0; k < 12; k++) W4[tid + 256 * k] = v[k];
    if (tail) W4[tid + 3072] = v12;
    SL[tid] = slacc;
    __syncthreads();

    float s1 = 0.f;
    const float* wr = W + tid * EE;
#pragma unroll
    for (int i = 0; i < EE; i++) s1 += wr[i];
    g_M[(size_t)(b * SS + s0 + (tid >> 7)) * SS + (tid & 127)] = (s1 + SL[tid]) * (1.0f / EE);
}

// =======================================================================
// k_compute: per (b, 4-row group), 256 blocks x 256 threads.
// Phase 3 handles D=300 > 256 threads (second feature jB = tid+256
// for tid<44 participates in LN sums and stores).
// =======================================================================
#define OFF_MS    0        // 512 f : packed M f2 [t*2+rp]
#define OFF_AX    512      // 1200 f: AxP f2 [d*2+rp]
#define OFF_NS    1712     // 1200 f: g/node f2 [j*2+rp]
#define OFF_GH    2912     // 2400 f: 1200 ull combine scratch
#define OFF_RED   5312     // 32
#define OFF_MEAN  5344     // 4
#define OFF_INVD  5348     // 4
#define SMEM_FLOATS 5352
#define SMEM_BYTES  (SMEM_FLOATS * 4)

__global__ __launch_bounds__(NTHR, 2) void k_compute(
    const float* __restrict__ x,   const float* __restrict__ Wb,
    const float* __restrict__ lna, const float* __restrict__ lnb,
    float* __restrict__ node_out)
{
    extern __shared__ float sm[];
    float*  MsPf  = sm + OFF_MS;
    float2* MsP   = reinterpret_cast<float2*>(MsPf);
    float2* AxP   = reinterpret_cast<float2*>(sm + OFF_AX);
    float2* NsP   = reinterpret_cast<float2*>(sm + OFF_NS);
    ull*    GH    = reinterpret_cast<ull*>(sm + OFF_GH);
    float*  red   = sm + OFF_RED;
    float*  means = sm + OFF_MEAN;
    float*  invd  = sm + OFF_INVD;

    const int tid = threadIdx.x;
    const int b   = blockIdx.x >> 5;             // / 32 groups
    const int s0  = (blockIdx.x & 31) * RROWS;

    // ---- stage + pack this block's 4 M rows ----
    if (tid < 128) {
        float4 v = reinterpret_cast<const float4*>(g_M + (size_t)(b * SS + s0) * SS)[tid];
        int r = tid >> 5, t0 = (tid & 31) * 4;
        float vals[4] = {v.x, v.y, v.z, v.w};
#pragma unroll
        for (int k = 0; k < 4; k++) {
            int t = t0 + k;
            MsPf[(t * 2 + (r >> 1)) * 2 + (r & 1)] = vals[k];
        }
    }
    __syncthreads();

    // ========== Phase 1: Ax[r][d] = sum_t M[r][t] x[t][d] ==========
    ull acc1[4][2];
#pragma unroll
    for (int r = 0; r < 4; r++) { acc1[r][0] = 0; acc1[r][1] = 0; }
    if (tid < 150) {
        const int tseg = tid / 75, dq = tid % 75, d0 = dq * 4;
        const float* xb = x + (size_t)b * SS * DD + d0;
        const int t0 = tseg * 64;
#pragma unroll 2
        for (int tb = 0; tb < 8; tb++) {
            float4 xq[8];
#pragma unroll
            for (int u = 0; u < 8; u++)
                xq[u] = *reinterpret_cast<const float4*>(xb + (size_t)(t0 + tb * 8 + u) * DD);
#pragma unroll
            for (int u = 0; u < 8; u++) {
                const int t = t0 + tb * 8 + u;
                float2 m01 = MsP[t * 2], m23 = MsP[t * 2 + 1];
                ull xlo = pk2(xq[u].x, xq[u].y), xhi = pk2(xq[u].z, xq[u].w);
                fma2p(acc1[0], m01.x, xlo, xhi);
                fma2p(acc1[1], m01.y, xlo, xhi);
                fma2p(acc1[2], m23.x, xlo, xhi);
                fma2p(acc1[3], m23.y, xlo, xhi);
            }
        }
        if (tseg) {
            ull* g = GH + dq * 8;
#pragma unroll
            for (int r = 0; r < 4; r++) { g[r * 2] = acc1[r][0]; g[r * 2 + 1] = acc1[r][1]; }
        }
    }
    __syncthreads();
    if (tid < 75) {
        const ull* g = GH + tid * 8;
#pragma unroll
        for (int r = 0; r < 4; r++) {
            acc1[r][0] = f2add(acc1[r][0], g[r * 2]);
            acc1[r][1] = f2add(acc1[r][1], g[r * 2 + 1]);
        }
        float v[4][4];
#pragma unroll
        for (int r = 0; r < 4; r++) {
            upk2(acc1[r][0], v[r][0], v[r][1]);
            upk2(acc1[r][1], v[r][2], v[r][3]);
        }
        const int d0 = tid * 4;
#pragma unroll
        for (int dd = 0; dd < 4; dd++)
#pragma unroll
            for (int rp = 0; rp < 2; rp++)
                AxP[(d0 + dd) * 2 + rp] = make_float2(v[2 * rp][dd], v[2 * rp + 1][dd]);
    }
    __syncthreads();

    // ========== Phase 2: g = Ax @ W^T + b (d-thirds x j-quads) ==========
    ull acc2[4][2];
#pragma unroll
    for (int j = 0; j < 4; j++) { acc2[j][0] = 0; acc2[j][1] = 0; }
    const ulonglong2* AxV = reinterpret_cast<const ulonglong2*>(AxP);
    if (tid < 225) {
        const int seg = tid / 75, jg = tid % 75;
        const int d0 = seg * 100, j0 = jg * 4;
        const float* wtb = g_Wt + j0;
#pragma unroll 5
        for (int u = 0; u < 50; u++) {
            int d = d0 + 2 * u;
            float4 wa  = *reinterpret_cast<const float4*>(wtb + (size_t)d * DD);
            float4 wb2 = *reinterpret_cast<const float4*>(wtb + (size_t)(d + 1) * DD);
            ulonglong2 A0 = AxV[d], A1 = AxV[d + 1];
            fma2p(acc2[0], wa.x,  A0.x, A0.y);
            fma2p(acc2[1], wa.y,  A0.x, A0.y);
            fma2p(acc2[2], wa.z,  A0.x, A0.y);
            fma2p(acc2[3], wa.w,  A0.x, A0.y);
            fma2p(acc2[0], wb2.x, A1.x, A1.y);
            fma2p(acc2[1], wb2.y, A1.x, A1.y);
            fma2p(acc2[2], wb2.z, A1.x, A1.y);
            fma2p(acc2[3], wb2.w, A1.x, A1.y);
        }
        if (seg) {
            ull* g = GH + (size_t)((seg - 1) * 75 + jg) * 8;
#pragma unroll
            for (int j = 0; j < 4; j++) { g[j * 2] = acc2[j][0]; g[j * 2 + 1] = acc2[j][1]; }
        }
    }
    __syncthreads();
    if (tid < 75) {
#pragma unroll
        for (int s = 0; s < 2; s++) {
            const ull* g = GH + (size_t)(s * 75 + tid) * 8;
#pragma unroll
            for (int j = 0; j < 4; j++) {
                acc2[j][0] = f2add(acc2[j][0], g[j * 2]);
                acc2[j][1] = f2add(acc2[j][1], g[j * 2 + 1]);
            }
        }
#pragma unroll
        for (int jj = 0; jj < 4; jj++) {
            int j = tid * 4 + jj;
            ull b2 = pk2(Wb[j], Wb[j]);
            *reinterpret_cast<ull*>(&NsP[j * 2])     = f2add(acc2[jj][0], b2);
            *reinterpret_cast<ull*>(&NsP[j * 2 + 1]) = f2add(acc2[jj][1], b2);
        }
    }
    __syncthreads();

    // ========== Phase 3: LayerNorm (ddof=1) + relu — handles 300 > 256 =====
    const int lane = tid & 31, warp = tid >> 5;
    const bool hasB = (tid < DD - NTHR);          // second feature jB = tid+256
    float gjA[4], gjB[4];
    {
        ulonglong2 a = reinterpret_cast<const ulonglong2*>(NsP)[tid];
        upk2(a.x, gjA[0], gjA[1]); upk2(a.y, gjA[2], gjA[3]);
        if (hasB) {
            ulonglong2 bq = reinterpret_cast<const ulonglong2*>(NsP)[tid + NTHR];
            upk2(bq.x, gjB[0], gjB[1]); upk2(bq.y, gjB[2], gjB[3]);
        }
    }
    {
        float s[4];
#pragma unroll
        for (int r = 0; r < 4; r++) s[r] = gjA[r] + (hasB ? gjB[r] : 0.f);
#pragma unroll
        for (int off = 16; off; off >>= 1)
#pragma unroll
            for (int r = 0; r < 4; r++) s[r] += __shfl_down_sync(0xffffffffu, s[r], off);
        if (lane == 0)
#pragma unroll
            for (int r = 0; r < 4; r++) red[warp * 4 + r] = s[r];
    }
    __syncthreads();
    if (tid < 4) {
        float s = 0.f;
#pragma unroll
        for (int w = 0; w < NTHR / 32; w++) s += red[w * 4 + tid];
        means[tid] = s * (1.0f / DD);
    }
    __syncthreads();
    {
        float s[4];
#pragma unroll
        for (int r = 0; r < 4; r++) {
            float dA = gjA[r] - means[r];
            float dB = hasB ? (gjB[r] - means[r]) : 0.f;
            s[r] = dA * dA + dB * dB;
        }
#pragma unroll
        for (int off = 16; off; off >>= 1)
#pragma unroll
            for (int r = 0; r < 4; r++) s[r] += __shfl_down_sync(0xffffffffu, s[r], off);
        if (lane == 0)
#pragma unroll
            for (int r = 0; r < 4; r++) red[warp * 4 + r] = s[r];
    }
    __syncthreads();
    if (tid < 4) {
        float s = 0.f;
#pragma unroll
        for (int w = 0; w < NTHR / 32; w++) s += red[w * 4 + tid];
        float stdv = sqrtf(s * (1.0f / (DD - 1)));   // ddof = 1
        invd[tid] = 1.0f / (stdv + 1e-6f);
    }
    __syncthreads();

    {
        float aA = lna[tid], bA = lnb[tid];
        float nvA[4];
#pragma unroll
        for (int r = 0; r < 4; r++) {
            float v = aA * (gjA[r] - means[r]) * invd[r] + bA;
            nvA[r] = v > 0.f ? v : 0.f;
            node_out[(size_t)(b * SS + s0 + r) * DD + tid] = nvA[r];
        }
        if (hasB) {
            int jB = tid + NTHR;
            float aB = lna[jB], bB = lnb[jB];
            float nvB[4];
#pragma unroll
            for (int r = 0; r < 4; r++) {
                float v = aB * (gjB[r] - means[r]) * invd[r] + bB;
                nvB[r] = v > 0.f ? v : 0.f;
                node_out[(size_t)(b * SS + s0 + r) * DD + jB] = nvB[r];
            }
            NsP[jB * 2]     = make_float2(nvB[0], nvB[1]);
            NsP[jB * 2 + 1] = make_float2(nvB[2], nvB[3]);
        }
        __syncwarp();
        NsP[tid * 2]     = make_float2(nvA[0], nvA[1]);
        NsP[tid * 2 + 1] = make_float2(nvA[2], nvA[3]);
    }
    __syncthreads();

    // ========== Phase 4: P = node @ W1^T (d-sixths x o-quads) ==========
    ull acc4[4][2];
#pragma unroll
    for (int j = 0; j < 4; j++) { acc4[j][0] = 0; acc4[j][1] = 0; }
    const ulonglong2* NsV = reinterpret_cast<const ulonglong2*>(NsP);
    if (tid < 150) {
        const int seg = tid / 25, og = tid % 25;
        const int d0 = seg * 50, o0 = og * 4;
#pragma unroll 5
        for (int u = 0; u < 25; u++) {
            int d = d0 + 2 * u;
            float4 wa  = *reinterpret_cast<const float4*>(g_W1t + (size_t)d * 100 + o0);
            float4 wb2 = *reinterpret_cast<const float4*>(g_W1t + (size_t)(d + 1) * 100 + o0);
            ulonglong2 N0 = NsV[d], N1 = NsV[d + 1];
            fma2p(acc4[0], wa.x,  N0.x, N0.y);
            fma2p(acc4[1], wa.y,  N0.x, N0.y);
            fma2p(acc4[2], wa.z,  N0.x, N0.y);
            fma2p(acc4[3], wa.w,  N0.x, N0.y);
            fma2p(acc4[0], wb2.x, N1.x, N1.y);
            fma2p(acc4[1], wb2.y, N1.x, N1.y);
            fma2p(acc4[2], wb2.z, N1.x, N1.y);
            fma2p(acc4[3], wb2.w, N1.x, N1.y);
        }
        if (seg) {
            ull* g = GH + (size_t)((seg - 1) * 25 + og) * 8;
#pragma unroll
            for (int j = 0; j < 4; j++) { g[j * 2] = acc4[j][0]; g[j * 2 + 1] = acc4[j][1]; }
        }
    }
    __syncthreads();
    if (tid < 25) {
#pragma unroll
        for (int s = 0; s < 5; s++) {
            const ull* g = GH + (size_t)(s * 25 + tid) * 8;
#pragma unroll
            for (int j = 0; j < 4; j++) {
                acc4[j][0] = f2add(acc4[j][0], g[j * 2]);
                acc4[j][1] = f2add(acc4[j][1], g[j * 2 + 1]);
            }
        }
#pragma unroll
        for (int jj = 0; jj < 4; jj++) {
            int o = tid * 4 + jj, e = o >> 1;
            float* dst = ((o & 1) ? g_Pb : g_Pa) + (size_t)(b * SS + s0) * DEPC + e;
#pragma unroll
            for (int rp = 0; rp < 2; rp++) {
                float f0, f1;
                upk2(acc4[jj][rp], f0, f1);
                dst[(2 * rp) * DEPC]     = f0;
                dst[(2 * rp + 1) * DEPC] = f1;
            }
        }
    }
}

// =======================================================================
// k_edge (unchanged)
// =======================================================================
__global__ __launch_bounds__(800) void k_edge(const float* __restrict__ W1b,
                                              float* __restrict__ edge) {
    const int bi0 = blockIdx.x * 2;
    const int b   = bi0 >> 7;
    const int tid = threadIdx.x;
    const int e2  = tid % 25;
    const int j0  = tid / 25;

    float2 w = reinterpret_cast<const float2*>(W1b)[e2];
    const ull* pa = reinterpret_cast<const ull*>(g_Pa + (size_t)b * SS * DEPC);
    ull pav[4];
#pragma unroll
    for (int k = 0; k < 4; k++) pav[k] = pa[(j0 + 32 * k) * 25 + e2];

#pragma unroll
    for (int r = 0; r < 2; r++) {
        int bi = bi0 + r;
        float2 pv = reinterpret_cast<const float2*>(g_Pb + (size_t)bi * DEPC)[e2];
        ull pr = pk2(pv.x + w.x, pv.y + w.y);
        ull* out = reinterpret_cast<ull*>(edge + (size_t)bi * SS * DEPC);
#pragma unroll
        for (int k = 0; k < 4; k++) out[(j0 + 32 * k) * 25 + e2] = f2add(pav[k], pr);
    }
}

// =======================================================================
extern "C" void kernel_launch(void* const* d_in, const int* in_sizes, int n_in,
                              void* d_out, int out_size) {
    const float* wps = (const float*)d_in[0];
    /* d_in[1] = weight_adj (int64) — unused */
    const float* x   = (const float*)d_in[2];
    const float* sl  = (const float*)d_in[3];
    const float* Ww  = (const float*)d_in[4];
    const float* Wb  = (const float*)d_in[5];
    const float* lna = (const float*)d_in[6];
    const float* lnb = (const float*)d_in[7];
    const float* W1w = (const float*)d_in[8];
    const float* W1b = (const float*)d_in[9];

    float* out  = (float*)d_out;
    float* node = out;
    float* edge = out + BB * SS * DD;

    cudaFuncSetAttribute((const void*)k_reduce,
                         cudaFuncAttributeMaxDynamicSharedMemorySize, RED_SMEM_BYTES);
    cudaFuncSetAttribute((const void*)k_compute,
                         cudaFuncAttributeMaxDynamicSharedMemorySize, SMEM_BYTES);

    k_prep_w <<<120, 256>>>(Ww, W1w);
    k_pref_x <<<150, 256>>>(x);
    k_reduce <<<BB * SS / 2, 256, RED_SMEM_BYTES>>>(wps, sl);
    k_compute<<<BB * (SS / RROWS), NTHR, SMEM_BYTES>>>(x, Wb, lna, lnb, node);
    k_edge   <<<BB * SS / 2, 800>>>(W1b, edge);
}

// round 16
// speedup vs baseline: 1.1092x; 1.0017x over previous
#include <cuda_runtime.h>
#include <cstdint>

#define BB   8
#define SS   128
#define DD   300
#define EE   50
#define DEPC 50
#define RROWS 4
#define NTHR 256

__device__ float g_M  [BB * SS * SS];
__device__ float g_Wt [DD * DD];        // Wt[d][j]  = Ww[j][d]
__device__ float g_W1t[DD * 100];       // W1t[d][o] = W1w[o>>1][(o&1)*300 + d]
__device__ float g_Pa [BB * SS * DEPC];
__device__ float g_Pb [BB * SS * DEPC];

using ull = unsigned long long;

__device__ __forceinline__ ull pk2(float x, float y) {
    ull r; asm("mov.b64 %0, {%1,%2};" : "=l"(r) : "f"(x), "f"(y)); return r;
}
__device__ __forceinline__ ull f2fma(ull a, ull b, ull c) {
    ull d; asm("fma.rn.f32x2 %0, %1, %2, %3;" : "=l"(d) : "l"(a), "l"(b), "l"(c)); return d;
}
__device__ __forceinline__ ull f2add(ull a, ull b) {
    ull d; asm("add.rn.f32x2 %0, %1, %2;" : "=l"(d) : "l"(a), "l"(b)); return d;
}
__device__ __forceinline__ void upk2(ull v, float& x, float& y) {
    asm("mov.b64 {%0,%1}, %2;" : "=f"(x), "=f"(y) : "l"(v));
}
__device__ __forceinline__ void fma2p(ull* a, float w, ull r0, ull r1) {
    ull ww = pk2(w, w);
    a[0] = f2fma(ww, r0, a[0]); a[1] = f2fma(ww, r1, a[1]);
}

// =======================================================================
// k_prep_w / k_pref_x  (launch order keeps ncu -s5-c1 on k_compute)
// =======================================================================
__global__ void k_prep_w(const float* __restrict__ Ww, const float* __restrict__ W1w) {
    const int bid = blockIdx.x;
    const int tid = threadIdx.x;
    if (bid < 100) {
        __shared__ float tile[32][33];
        const int jt = (bid / 10) * 32, dt = (bid % 10) * 32;
        const int tx = tid & 31, ty = tid >> 5;
#pragma unroll
        for (int yy = ty; yy < 32; yy += 8) {
            int j = jt + yy, d = dt + tx;
            tile[yy][tx] = (j < DD && d < DD) ? Ww[j * DD + d] : 0.f;
        }
        __syncthreads();
#pragma unroll
        for (int yy = ty; yy < 32; yy += 8) {
            int d = dt + yy, j = jt + tx;
            if (d < DD && j < DD) g_Wt[d * DD + j] = tile[tx][yy];
        }
    } else {
        for (int idx = (bid - 100) * 256 + tid; idx < 100 * DD; idx += 20 * 256) {
            int e = idx / 600, c = idx - e * 600;
            int d = c % DD, half = c / DD;
            g_W1t[d * 100 + 2 * e + half] = W1w[idx];
        }
    }
}
__global__ void k_pref_x(const float* __restrict__ x) {
    int i = blockIdx.x * blockDim.x + threadIdx.x;
    float v = 0.f;
    if (i < 38400) v = x[i * 8];
    asm volatile("" :: "f"(v));
}

// =======================================================================
// k_reduce (unchanged)
// =======================================================================
#define RED_SMEM_FLOATS (2 * 128 * EE + 256)
#define RED_SMEM_BYTES  (RED_SMEM_FLOATS * 4)

__global__ __launch_bounds__(256, 3) void k_reduce(const float* __restrict__ wps,
                                                   const float* __restrict__ sl) {
    extern __shared__ float rsm[];
    float* W  = rsm;
    float* SL = rsm + 2 * 128 * EE;
    const int tid = threadIdx.x;
    const int blk = blockIdx.x;
    const int b   = blk >> 6;
    const int s0  = (blk & 63) * 2;

    const float4* src = reinterpret_cast<const float4*>(wps) + (size_t)(b * SS + s0) * 1600;
    float4* W4 = reinterpret_cast<float4*>(W);
    float4 v[12];
#pragma unroll
    for (int k = 0; k < 12; k++) v[k] = src[tid + 256 * k];
    float4 v12;
    const bool tail = tid < 128;
    if (tail) v12 = src[tid + 3072];

    float slacc;
    {
        const float* sp_ = sl + (size_t)b * EE * SS * SS + (s0 + (tid >> 7)) * SS + (tid & 127);
        float p[5] = {0.f, 0.f, 0.f, 0.f, 0.f};
#pragma unroll
        for (int e = 0; e < EE; e++) p[e % 5] += sp_[(size_t)e * SS * SS];
        slacc = (p[0] + p[1]) + (p[2] + p[3]) + p[4];
    }

#pragma unroll
    for (int k = 0; k < 12; k++) W4[tid + 256 * k] = v[k];
    if (tail) W4[tid + 3072] = v12;
    SL[tid] = slacc;
    __syncthreads();

    float s1 = 0.f;
    const float* wr = W + tid * EE;
#pragma unroll
    for (int i = 0; i < EE; i++) s1 += wr[i];
    g_M[(size_t)(b * SS + s0 + (tid >> 7)) * SS + (tid & 127)] = (s1 + SL[tid]) * (1.0f / EE);
}

// =======================================================================
// k_compute: per (b, 4-row group), 256 blocks x 256 threads, 3 blocks/SM.
// =======================================================================
#define OFF_MS    0        // 512 f : packed M f2 [t*2+rp]
#define OFF_AX    512      // 1200 f: AxP f2 [d*2+rp]
#define OFF_NS    1712     // 1200 f: g/node f2 [j*2+rp]
#define OFF_GH    2912     // 2400 f: 1200 ull combine scratch
#define OFF_RED   5312     // 32
#define OFF_MEAN  5344     // 4
#define OFF_INVD  5348     // 4
#define SMEM_FLOATS 5352
#define SMEM_BYTES  (SMEM_FLOATS * 4)

__global__ __launch_bounds__(NTHR, 3) void k_compute(
    const float* __restrict__ x,   const float* __restrict__ Wb,
    const float* __restrict__ lna, const float* __restrict__ lnb,
    float* __restrict__ node_out)
{
    extern __shared__ float sm[];
    float*  MsPf  = sm + OFF_MS;
    float2* MsP   = reinterpret_cast<float2*>(MsPf);
    float2* AxP   = reinterpret_cast<float2*>(sm + OFF_AX);
    float2* NsP   = reinterpret_cast<float2*>(sm + OFF_NS);
    ull*    GH    = reinterpret_cast<ull*>(sm + OFF_GH);
    float*  red   = sm + OFF_RED;
    float*  means = sm + OFF_MEAN;
    float*  invd  = sm + OFF_INVD;

    const int tid = threadIdx.x;
    const int b   = blockIdx.x >> 5;             // / 32 groups
    const int s0  = (blockIdx.x & 31) * RROWS;

    // ---- stage + pack this block's 4 M rows ----
    if (tid < 128) {
        float4 v = reinterpret_cast<const float4*>(g_M + (size_t)(b * SS + s0) * SS)[tid];
        int r = tid >> 5, t0 = (tid & 31) * 4;
        float vals[4] = {v.x, v.y, v.z, v.w};
#pragma unroll
        for (int k = 0; k < 4; k++) {
            int t = t0 + k;
            MsPf[(t * 2 + (r >> 1)) * 2 + (r & 1)] = vals[k];
        }
    }
    __syncthreads();

    // ========== Phase 1: Ax[r][d] = sum_t M[r][t] x[t][d] ==========
    ull acc1[4][2];
#pragma unroll
    for (int r = 0; r < 4; r++) { acc1[r][0] = 0; acc1[r][1] = 0; }
    if (tid < 150) {
        const int tseg = tid / 75, dq = tid % 75, d0 = dq * 4;
        const float* xb = x + (size_t)b * SS * DD + d0;
        const int t0 = tseg * 64;
#pragma unroll 2
        for (int tb = 0; tb < 16; tb++) {
            float4 xq[4];
#pragma unroll
            for (int u = 0; u < 4; u++)
                xq[u] = *reinterpret_cast<const float4*>(xb + (size_t)(t0 + tb * 4 + u) * DD);
#pragma unroll
            for (int u = 0; u < 4; u++) {
                const int t = t0 + tb * 4 + u;
                float2 m01 = MsP[t * 2], m23 = MsP[t * 2 + 1];
                ull xlo = pk2(xq[u].x, xq[u].y), xhi = pk2(xq[u].z, xq[u].w);
                fma2p(acc1[0], m01.x, xlo, xhi);
                fma2p(acc1[1], m01.y, xlo, xhi);
                fma2p(acc1[2], m23.x, xlo, xhi);
                fma2p(acc1[3], m23.y, xlo, xhi);
            }
        }
        if (tseg) {
            ull* g = GH + dq * 8;
#pragma unroll
            for (int r = 0; r < 4; r++) { g[r * 2] = acc1[r][0]; g[r * 2 + 1] = acc1[r][1]; }
        }
    }
    __syncthreads();
    if (tid < 75) {
        const ull* g = GH + tid * 8;
#pragma unroll
        for (int r = 0; r < 4; r++) {
            acc1[r][0] = f2add(acc1[r][0], g[r * 2]);
            acc1[r][1] = f2add(acc1[r][1], g[r * 2 + 1]);
        }
        float v[4][4];
#pragma unroll
        for (int r = 0; r < 4; r++) {
            upk2(acc1[r][0], v[r][0], v[r][1]);
            upk2(acc1[r][1], v[r][2], v[r][3]);
        }
        const int d0 = tid * 4;
#pragma unroll
        for (int dd = 0; dd < 4; dd++)
#pragma unroll
            for (int rp = 0; rp < 2; rp++)
                AxP[(d0 + dd) * 2 + rp] = make_float2(v[2 * rp][dd], v[2 * rp + 1][dd]);
    }
    __syncthreads();

    // ========== Phase 2: g = Ax @ W^T + b (d-thirds x j-quads) ==========
    ull acc2[4][2];
#pragma unroll
    for (int j = 0; j < 4; j++) { acc2[j][0] = 0; acc2[j][1] = 0; }
    const ulonglong2* AxV = reinterpret_cast<const ulonglong2*>(AxP);
    if (tid < 225) {
        const int seg = tid / 75, jg = tid % 75;
        const int d0 = seg * 100, j0 = jg * 4;
        const float* wtb = g_Wt + j0;
#pragma unroll 5
        for (int u = 0; u < 50; u++) {
            int d = d0 + 2 * u;
            float4 wa  = *reinterpret_cast<const float4*>(wtb + (size_t)d * DD);
            float4 wb2 = *reinterpret_cast<const float4*>(wtb + (size_t)(d + 1) * DD);
            ulonglong2 A0 = AxV[d], A1 = AxV[d + 1];
            fma2p(acc2[0], wa.x,  A0.x, A0.y);
            fma2p(acc2[1], wa.y,  A0.x, A0.y);
            fma2p(acc2[2], wa.z,  A0.x, A0.y);
            fma2p(acc2[3], wa.w,  A0.x, A0.y);
            fma2p(acc2[0], wb2.x, A1.x, A1.y);
            fma2p(acc2[1], wb2.y, A1.x, A1.y);
            fma2p(acc2[2], wb2.z, A1.x, A1.y);
            fma2p(acc2[3], wb2.w, A1.x, A1.y);
        }
        if (seg) {
            ull* g = GH + (size_t)((seg - 1) * 75 + jg) * 8;
#pragma unroll
            for (int j = 0; j < 4; j++) { g[j * 2] = acc2[j][0]; g[j * 2 + 1] = acc2[j][1]; }
        }
    }
    __syncthreads();
    if (tid < 75) {
#pragma unroll
        for (int s = 0; s < 2; s++) {
            const ull* g = GH + (size_t)(s * 75 + tid) * 8;
#pragma unroll
            for (int j = 0; j < 4; j++) {
                acc2[j][0] = f2add(acc2[j][0], g[j * 2]);
                acc2[j][1] = f2add(acc2[j][1], g[j * 2 + 1]);
            }
        }
#pragma unroll
        for (int jj = 0; jj < 4; jj++) {
            int j = tid * 4 + jj;
            ull b2 = pk2(Wb[j], Wb[j]);
            *reinterpret_cast<ull*>(&NsP[j * 2])     = f2add(acc2[jj][0], b2);
            *reinterpret_cast<ull*>(&NsP[j * 2 + 1]) = f2add(acc2[jj][1], b2);
        }
    }
    __syncthreads();

    // ========== Phase 3: LayerNorm (ddof=1) + relu — handles 300 > 256 =====
    const int lane = tid & 31, warp = tid >> 5;
    const bool hasB = (tid < DD - NTHR);          // second feature jB = tid+256
    float gjA[4], gjB[4];
    {
        ulonglong2 a = reinterpret_cast<const ulonglong2*>(NsP)[tid];
        upk2(a.x, gjA[0], gjA[1]); upk2(a.y, gjA[2], gjA[3]);
        if (hasB) {
            ulonglong2 bq = reinterpret_cast<const ulonglong2*>(NsP)[tid + NTHR];
            upk2(bq.x, gjB[0], gjB[1]); upk2(bq.y, gjB[2], gjB[3]);
        }
    }
    {
        float s[4];
#pragma unroll
        for (int r = 0; r < 4; r++) s[r] = gjA[r] + (hasB ? gjB[r] : 0.f);
#pragma unroll
        for (int off = 16; off; off >>= 1)
#pragma unroll
            for (int r = 0; r < 4; r++) s[r] += __shfl_down_sync(0xffffffffu, s[r], off);
        if (lane == 0)
#pragma unroll
            for (int r = 0; r < 4; r++) red[warp * 4 + r] = s[r];
    }
    __syncthreads();
    if (tid < 4) {
        float s = 0.f;
#pragma unroll
        for (int w = 0; w < NTHR / 32; w++) s += red[w * 4 + tid];
        means[tid] = s * (1.0f / DD);
    }
    __syncthreads();
    {
        float s[4];
#pragma unroll
        for (int r = 0; r < 4; r++) {
            float dA = gjA[r] - means[r];
            float dB = hasB ? (gjB[r] - means[r]) : 0.f;
            s[r] = dA * dA + dB * dB;
        }
#pragma unroll
        for (int off = 16; off; off >>= 1)
#pragma unroll
            for (int r = 0; r < 4; r++) s[r] += __shfl_down_sync(0xffffffffu, s[r], off);
        if (lane == 0)
#pragma unroll
            for (int r = 0; r < 4; r++) red[warp * 4 + r] = s[r];
    }
    __syncthreads();
    if (tid < 4) {
        float s = 0.f;
#pragma unroll
        for (int w = 0; w < NTHR / 32; w++) s += red[w * 4 + tid];
        float stdv = sqrtf(s * (1.0f / (DD - 1)));   // ddof = 1
        invd[tid] = 1.0f / (stdv + 1e-6f);
    }
    __syncthreads();

    {
        float aA = lna[tid], bA = lnb[tid];
        float nvA[4];
#pragma unroll
        for (int r = 0; r < 4; r++) {
            float v = aA * (gjA[r] - means[r]) * invd[r] + bA;
            nvA[r] = v > 0.f ? v : 0.f;
            node_out[(size_t)(b * SS + s0 + r) * DD + tid] = nvA[r];
        }
        if (hasB) {
            int jB = tid + NTHR;
            float aB = lna[jB], bB = lnb[jB];
            float nvB[4];
#pragma unroll
            for (int r = 0; r < 4; r++) {
                float v = aB * (gjB[r] - means[r]) * invd[r] + bB;
                nvB[r] = v > 0.f ? v : 0.f;
                node_out[(size_t)(b * SS + s0 + r) * DD + jB] = nvB[r];
            }
            NsP[jB * 2]     = make_float2(nvB[0], nvB[1]);
            NsP[jB * 2 + 1] = make_float2(nvB[2], nvB[3]);
        }
        __syncwarp();
        NsP[tid * 2]     = make_float2(nvA[0], nvA[1]);
        NsP[tid * 2 + 1] = make_float2(nvA[2], nvA[3]);
    }
    __syncthreads();

    // ========== Phase 4: P = node @ W1^T (o-pairs x 5 d-segs, 250 thr) =====
    ull acc4[2][2];
#pragma unroll
    for (int j = 0; j < 2; j++) { acc4[j][0] = 0; acc4[j][1] = 0; }
    const ulonglong2* NsV = reinterpret_cast<const ulonglong2*>(NsP);
    if (tid < 250) {
        const int seg = tid / 50, op = tid % 50;
        const int d0 = seg * 60, o0 = op * 2;
#pragma unroll 5
        for (int u = 0; u < 30; u++) {
            int d = d0 + 2 * u;
            float2 wa  = *reinterpret_cast<const float2*>(g_W1t + (size_t)d * 100 + o0);
            float2 wb2 = *reinterpret_cast<const float2*>(g_W1t + (size_t)(d + 1) * 100 + o0);
            ulonglong2 N0 = NsV[d], N1 = NsV[d + 1];
            fma2p(acc4[0], wa.x,  N0.x, N0.y);
            fma2p(acc4[1], wa.y,  N0.x, N0.y);
            fma2p(acc4[0], wb2.x, N1.x, N1.y);
            fma2p(acc4[1], wb2.y, N1.x, N1.y);
        }
        if (seg) {
            ull* g = GH + (size_t)((seg - 1) * 50 + op) * 4;
#pragma unroll
            for (int j = 0; j < 2; j++) { g[j * 2] = acc4[j][0]; g[j * 2 + 1] = acc4[j][1]; }
        }
    }
    __syncthreads();
    if (tid < 50) {
#pragma unroll
        for (int s = 0; s < 4; s++) {
            const ull* g = GH + (size_t)(s * 50 + tid) * 4;
#pragma unroll
            for (int j = 0; j < 2; j++) {
                acc4[j][0] = f2add(acc4[j][0], g[j * 2]);
                acc4[j][1] = f2add(acc4[j][1], g[j * 2 + 1]);
            }
        }
#pragma unroll
        for (int jj = 0; jj < 2; jj++) {
            int o = tid * 2 + jj, e = o >> 1;
            float* dst = ((o & 1) ? g_Pb : g_Pa) + (size_t)(b * SS + s0) * DEPC + e;
#pragma unroll
            for (int rp = 0; rp < 2; rp++) {
                float f0, f1;
                upk2(acc4[jj][rp], f0, f1);
                dst[(2 * rp) * DEPC]     = f0;
                dst[(2 * rp + 1) * DEPC] = f1;
            }
        }
    }
}

// =======================================================================
// k_edge (unchanged)
// =======================================================================
__global__ __launch_bounds__(800) void k_edge(const float* __restrict__ W1b,
                                              float* __restrict__ edge) {
    const int bi0 = blockIdx.x * 2;
    const int b   = bi0 >> 7;
    const int tid = threadIdx.x;
    const int e2  = tid % 25;
    const int j0  = tid / 25;

    float2 w = reinterpret_cast<const float2*>(W1b)[e2];
    const ull* pa = reinterpret_cast<const ull*>(g_Pa + (size_t)b * SS * DEPC);
    ull pav[4];
#pragma unroll
    for (int k = 0; k < 4; k++) pav[k] = pa[(j0 + 32 * k) * 25 + e2];

#pragma unroll
    for (int r = 0; r < 2; r++) {
        int bi = bi0 + r;
        float2 pv = reinterpret_cast<const float2*>(g_Pb + (size_t)bi * DEPC)[e2];
        ull pr = pk2(pv.x + w.x, pv.y + w.y);
        ull* out = reinterpret_cast<ull*>(edge + (size_t)bi * SS * DEPC);
#pragma unroll
        for (int k = 0; k < 4; k++) out[(j0 + 32 * k) * 25 + e2] = f2add(pav[k], pr);
    }
}

// =======================================================================
extern "C" void kernel_launch(void* const* d_in, const int* in_sizes, int n_in,
                              void* d_out, int out_size) {
    const float* wps = (const float*)d_in[0];
    /* d_in[1] = weight_adj (int64) — unused */
    const float* x   = (const float*)d_in[2];
    const float* sl  = (const float*)d_in[3];
    const float* Ww  = (const float*)d_in[4];
    const float* Wb  = (const float*)d_in[5];
    const float* lna = (const float*)d_in[6];
    const float* lnb = (const float*)d_in[7];
    const float* W1w = (const float*)d_in[8];
    const float* W1b = (const float*)d_in[9];

    float* out  = (float*)d_out;
    float* node = out;
    float* edge = out + BB * SS * DD;

    cudaFuncSetAttribute((const void*)k_reduce,
                         cudaFuncAttributeMaxDynamicSharedMemorySize, RED_SMEM_BYTES);
    cudaFuncSetAttribute((const void*)k_compute,
                         cudaFuncAttributeMaxDynamicSharedMemorySize, SMEM_BYTES);

    k_prep_w <<<120, 256>>>(Ww, W1w);
    k_pref_x <<<150, 256>>>(x);
    k_reduce <<<BB * SS / 2, 256, RED_SMEM_BYTES>>>(wps, sl);
    k_compute<<<BB * (SS / RROWS), NTHR, SMEM_BYTES>>>(x, Wb, lna, lnb, node);
    k_edge   <<<BB * SS / 2, 800>>>(W1b, edge);
}

// round 17
// speedup vs baseline: 1.2476x; 1.1248x over previous
#include <cuda_runtime.h>
#include <cstdint>

#define BB   8
#define SS   128
#define DD   300
#define EE   50
#define DEPC 50
#define RROWS 4
#define NTHR 256

__device__ float g_Wt [DD * DD];        // Wt[d][j]  = Ww[j][d]
__device__ float g_W1t[DD * 100];       // W1t[d][o] = W1w[o>>1][(o&1)*300 + d]
__device__ float g_Pa [BB * SS * DEPC];
__device__ float g_Pb [BB * SS * DEPC];

using ull = unsigned long long;

__device__ __forceinline__ ull pk2(float x, float y) {
    ull r; asm("mov.b64 %0, {%1,%2};" : "=l"(r) : "f"(x), "f"(y)); return r;
}
__device__ __forceinline__ ull f2fma(ull a, ull b, ull c) {
    ull d; asm("fma.rn.f32x2 %0, %1, %2, %3;" : "=l"(d) : "l"(a), "l"(b), "l"(c)); return d;
}
__device__ __forceinline__ ull f2add(ull a, ull b) {
    ull d; asm("add.rn.f32x2 %0, %1, %2;" : "=l"(d) : "l"(a), "l"(b)); return d;
}
__device__ __forceinline__ void upk2(ull v, float& x, float& y) {
    asm("mov.b64 {%0,%1}, %2;" : "=f"(x), "=f"(y) : "l"(v));
}
__device__ __forceinline__ void fma2p(ull* a, float w, ull r0, ull r1) {
    ull ww = pk2(w, w);
    a[0] = f2fma(ww, r0, a[0]); a[1] = f2fma(ww, r1, a[1]);
}

// =======================================================================
// k_prep: transpose W -> g_Wt, scatter W1 -> g_W1t, prefetch x into L2.
// =======================================================================
__global__ void k_prep(const float* __restrict__ Ww, const float* __restrict__ W1w,
                       const float* __restrict__ x) {
    const int bid = blockIdx.x;
    const int tid = threadIdx.x;
    if (bid < 100) {
        __shared__ float tile[32][33];
        const int jt = (bid / 10) * 32, dt = (bid % 10) * 32;
        const int tx = tid & 31, ty = tid >> 5;
#pragma unroll
        for (int yy = ty; yy < 32; yy += 8) {
            int j = jt + yy, d = dt + tx;
            tile[yy][tx] = (j < DD && d < DD) ? Ww[j * DD + d] : 0.f;
        }
        __syncthreads();
#pragma unroll
        for (int yy = ty; yy < 32; yy += 8) {
            int d = dt + yy, j = jt + tx;
            if (d < DD && j < DD) g_Wt[d * DD + j] = tile[tx][yy];
        }
    } else if (bid < 120) {
        for (int idx = (bid - 100) * 256 + tid; idx < 100 * DD; idx += 20 * 256) {
            int e = idx / 600, c = idx - e * 600;
            int d = c % DD, half = c / DD;
            g_W1t[d * 100 + 2 * e + half] = W1w[idx];
        }
    } else {
        int i = (bid - 120) * 256 + tid;
        float v = 0.f;
        if (i < 38400) v = x[i * 8];
        asm volatile("" :: "f"(v));
    }
}

// =======================================================================
// k_fused: per (b, 4-row group), 256 blocks x 256 threads, 2 blocks/SM.
// Phase 0 computes this block's 4 M rows in-kernel (coalesced wps staging
// through a 2-row smem buffer; sl strided loads); reduce launch + g_M
// round trip eliminated.  Phases 1-4 as R15.
// =======================================================================
#define OFF_MS    0        // 512 f : packed M f2 [t*2+rp]
#define OFF_AX    512      // 1200 f: AxP f2 [d*2+rp]
#define OFF_NS    1712     // 1200 f: g/node f2 [j*2+rp]
#define OFF_GH    2912     // 2400 f: 1200 ull combine scratch
#define OFF_RED   5312     // 32
#define OFF_MEAN  5344     // 4
#define OFF_INVD  5348     // 4
#define OFF_WBUF  5352     // 12800 f: two wps rows staged (51.2 KB)
#define SMEM_FLOATS (5352 + 12800)
#define SMEM_BYTES  (SMEM_FLOATS * 4)

__global__ __launch_bounds__(NTHR, 2) void k_fused(
    const float* __restrict__ wps, const float* __restrict__ sl,
    const float* __restrict__ x,   const float* __restrict__ Wb,
    const float* __restrict__ lna, const float* __restrict__ lnb,
    float* __restrict__ node_out)
{
    extern __shared__ float sm[];
    float*  MsPf  = sm + OFF_MS;
    float2* MsP   = reinterpret_cast<float2*>(MsPf);
    float2* AxP   = reinterpret_cast<float2*>(sm + OFF_AX);
    float2* NsP   = reinterpret_cast<float2*>(sm + OFF_NS);
    ull*    GH    = reinterpret_cast<ull*>(sm + OFF_GH);
    float*  red   = sm + OFF_RED;
    float*  means = sm + OFF_MEAN;
    float*  invd  = sm + OFF_INVD;
    float*  Wbuf  = sm + OFF_WBUF;

    const int tid = threadIdx.x;
    const int b   = blockIdx.x >> 5;             // / 32 groups
    const int s0  = (blockIdx.x & 31) * RROWS;

    // ================= Phase 0: M rows computed in-kernel =================
    // sl partials for both this thread's (r,t) tasks (tasks tid and tid+256)
    float slacc0, slacc1;
    {
        const int t = tid & 127, rlo = tid >> 7;
        const float* base = sl + (size_t)b * EE * SS * SS + t;
        const float* p0 = base + (size_t)(s0 + rlo) * SS;        // r = rlo
        const float* p1 = base + (size_t)(s0 + 2 + rlo) * SS;    // r = 2+rlo
        float a0 = 0.f, a1 = 0.f, a2 = 0.f, a3 = 0.f;
#pragma unroll
        for (int e = 0; e < EE; e += 2) {
            a0 += p0[(size_t)e * SS * SS];
            a1 += p0[(size_t)(e + 1) * SS * SS];
            a2 += p1[(size_t)e * SS * SS];
            a3 += p1[(size_t)(e + 1) * SS * SS];
        }
        slacc0 = a0 + a1; slacc1 = a2 + a3;
    }

#pragma unroll
    for (int h = 0; h < 2; h++) {
        // stage 2 wps rows (3200 float4) coalesced
        const float4* src = reinterpret_cast<const float4*>(wps)
                            + (size_t)(b * SS + s0 + h * 2) * 1600;
        float4* W4 = reinterpret_cast<float4*>(Wbuf);
        float4 v[12];
#pragma unroll
        for (int k = 0; k < 12; k++) v[k] = src[tid + 256 * k];
        float4 v12;
        const bool tail = tid < 128;
        if (tail) v12 = src[tid + 3072];
#pragma unroll
        for (int k = 0; k < 12; k++) W4[tid + 256 * k] = v[k];
        if (tail) W4[tid + 3072] = v12;
        __syncthreads();

        // rowsum: thread tid owns (r2 = tid>>7, t = tid&127) of this half
        float s1 = 0.f;
        const float* wr = Wbuf + tid * EE;
#pragma unroll
        for (int i = 0; i < EE; i++) s1 += wr[i];
        const int r = h * 2 + (tid >> 7), t = tid & 127;
        const float slv = h == 0 ? slacc0 : slacc1;
        MsPf[(t * 2 + (r >> 1)) * 2 + (r & 1)] = (s1 + slv) * (1.0f / EE);
        __syncthreads();
    }

    // ========== Phase 1: Ax[r][d] = sum_t M[r][t] x[t][d] ==========
    ull acc1[4][2];
#pragma unroll
    for (int r = 0; r < 4; r++) { acc1[r][0] = 0; acc1[r][1] = 0; }
    if (tid < 150) {
        const int tseg = tid / 75, dq = tid % 75, d0 = dq * 4;
        const float* xb = x + (size_t)b * SS * DD + d0;
        const int t0 = tseg * 64;
#pragma unroll 2
        for (int tb = 0; tb < 8; tb++) {
            float4 xq[8];
#pragma unroll
            for (int u = 0; u < 8; u++)
                xq[u] = *reinterpret_cast<const float4*>(xb + (size_t)(t0 + tb * 8 + u) * DD);
#pragma unroll
            for (int u = 0; u < 8; u++) {
                const int t = t0 + tb * 8 + u;
                float2 m01 = MsP[t * 2], m23 = MsP[t * 2 + 1];
                ull xlo = pk2(xq[u].x, xq[u].y), xhi = pk2(xq[u].z, xq[u].w);
                fma2p(acc1[0], m01.x, xlo, xhi);
                fma2p(acc1[1], m01.y, xlo, xhi);
                fma2p(acc1[2], m23.x, xlo, xhi);
                fma2p(acc1[3], m23.y, xlo, xhi);
            }
        }
        if (tseg) {
            ull* g = GH + dq * 8;
#pragma unroll
            for (int r = 0; r < 4; r++) { g[r * 2] = acc1[r][0]; g[r * 2 + 1] = acc1[r][1]; }
        }
    }
    __syncthreads();
    if (tid < 75) {
        const ull* g = GH + tid * 8;
#pragma unroll
        for (int r = 0; r < 4; r++) {
            acc1[r][0] = f2add(acc1[r][0], g[r * 2]);
            acc1[r][1] = f2add(acc1[r][1], g[r * 2 + 1]);
        }
        float v[4][4];
#pragma unroll
        for (int r = 0; r < 4; r++) {
            upk2(acc1[r][0], v[r][0], v[r][1]);
            upk2(acc1[r][1], v[r][2], v[r][3]);
        }
        const int d0 = tid * 4;
#pragma unroll
        for (int dd = 0; dd < 4; dd++)
#pragma unroll
            for (int rp = 0; rp < 2; rp++)
                AxP[(d0 + dd) * 2 + rp] = make_float2(v[2 * rp][dd], v[2 * rp + 1][dd]);
    }
    __syncthreads();

    // ========== Phase 2: g = Ax @ W^T + b (d-thirds x j-quads) ==========
    ull acc2[4][2];
#pragma unroll
    for (int j = 0; j < 4; j++) { acc2[j][0] = 0; acc2[j][1] = 0; }
    const ulonglong2* AxV = reinterpret_cast<const ulonglong2*>(AxP);
    if (tid < 225) {
        const int seg = tid / 75, jg = tid % 75;
        const int d0 = seg * 100, j0 = jg * 4;
        const float* wtb = g_Wt + j0;
#pragma unroll 5
        for (int u = 0; u < 50; u++) {
            int d = d0 + 2 * u;
            float4 wa  = *reinterpret_cast<const float4*>(wtb + (size_t)d * DD);
            float4 wb2 = *reinterpret_cast<const float4*>(wtb + (size_t)(d + 1) * DD);
            ulonglong2 A0 = AxV[d], A1 = AxV[d + 1];
            fma2p(acc2[0], wa.x,  A0.x, A0.y);
            fma2p(acc2[1], wa.y,  A0.x, A0.y);
            fma2p(acc2[2], wa.z,  A0.x, A0.y);
            fma2p(acc2[3], wa.w,  A0.x, A0.y);
            fma2p(acc2[0], wb2.x, A1.x, A1.y);
            fma2p(acc2[1], wb2.y, A1.x, A1.y);
            fma2p(acc2[2], wb2.z, A1.x, A1.y);
            fma2p(acc2[3], wb2.w, A1.x, A1.y);
        }
        if (seg) {
            ull* g = GH + (size_t)((seg - 1) * 75 + jg) * 8;
#pragma unroll
            for (int j = 0; j < 4; j++) { g[j * 2] = acc2[j][0]; g[j * 2 + 1] = acc2[j][1]; }
        }
    }
    __syncthreads();
    if (tid < 75) {
#pragma unroll
        for (int s = 0; s < 2; s++) {
            const ull* g = GH + (size_t)(s * 75 + tid) * 8;
#pragma unroll
            for (int j = 0; j < 4; j++) {
                acc2[j][0] = f2add(acc2[j][0], g[j * 2]);
                acc2[j][1] = f2add(acc2[j][1], g[j * 2 + 1]);
            }
        }
#pragma unroll
        for (int jj = 0; jj < 4; jj++) {
            int j = tid * 4 + jj;
            ull b2 = pk2(Wb[j], Wb[j]);
            *reinterpret_cast<ull*>(&NsP[j * 2])     = f2add(acc2[jj][0], b2);
            *reinterpret_cast<ull*>(&NsP[j * 2 + 1]) = f2add(acc2[jj][1], b2);
        }
    }
    __syncthreads();

    // ========== Phase 3: LayerNorm (ddof=1) + relu (300 > 256 threads) =====
    const int lane = tid & 31, warp = tid >> 5;
    const bool hasB = (tid < DD - NTHR);
    float gjA[4], gjB[4];
    {
        ulonglong2 a = reinterpret_cast<const ulonglong2*>(NsP)[tid];
        upk2(a.x, gjA[0], gjA[1]); upk2(a.y, gjA[2], gjA[3]);
        if (hasB) {
            ulonglong2 bq = reinterpret_cast<const ulonglong2*>(NsP)[tid + NTHR];
            upk2(bq.x, gjB[0], gjB[1]); upk2(bq.y, gjB[2], gjB[3]);
        }
    }
    {
        float s[4];
#pragma unroll
        for (int r = 0; r < 4; r++) s[r] = gjA[r] + (hasB ? gjB[r] : 0.f);
#pragma unroll
        for (int off = 16; off; off >>= 1)
#pragma unroll
            for (int r = 0; r < 4; r++) s[r] += __shfl_down_sync(0xffffffffu, s[r], off);
        if (lane == 0)
#pragma unroll
            for (int r = 0; r < 4; r++) red[warp * 4 + r] = s[r];
    }
    __syncthreads();
    if (tid < 4) {
        float s = 0.f;
#pragma unroll
        for (int w = 0; w < NTHR / 32; w++) s += red[w * 4 + tid];
        means[tid] = s * (1.0f / DD);
    }
    __syncthreads();
    {
        float s[4];
#pragma unroll
        for (int r = 0; r < 4; r++) {
            float dA = gjA[r] - means[r];
            float dB = hasB ? (gjB[r] - means[r]) : 0.f;
            s[r] = dA * dA + dB * dB;
        }
#pragma unroll
        for (int off = 16; off; off >>= 1)
#pragma unroll
            for (int r = 0; r < 4; r++) s[r] += __shfl_down_sync(0xffffffffu, s[r], off);
        if (lane == 0)
#pragma unroll
            for (int r = 0; r < 4; r++) red[warp * 4 + r] = s[r];
    }
    __syncthreads();
    if (tid < 4) {
        float s = 0.f;
#pragma unroll
        for (int w = 0; w < NTHR / 32; w++) s += red[w * 4 + tid];
        float stdv = sqrtf(s * (1.0f / (DD - 1)));   // ddof = 1
        invd[tid] = 1.0f / (stdv + 1e-6f);
    }
    __syncthreads();

    {
        float aA = lna[tid], bA = lnb[tid];
        float nvA[4];
#pragma unroll
        for (int r = 0; r < 4; r++) {
            float v = aA * (gjA[r] - means[r]) * invd[r] + bA;
            nvA[r] = v > 0.f ? v : 0.f;
            node_out[(size_t)(b * SS + s0 + r) * DD + tid] = nvA[r];
        }
        if (hasB) {
            int jB = tid + NTHR;
            float aB = lna[jB], bB = lnb[jB];
            float nvB[4];
#pragma unroll
            for (int r = 0; r < 4; r++) {
                float v = aB * (gjB[r] - means[r]) * invd[r] + bB;
                nvB[r] = v > 0.f ? v : 0.f;
                node_out[(size_t)(b * SS + s0 + r) * DD + jB] = nvB[r];
            }
            NsP[jB * 2]     = make_float2(nvB[0], nvB[1]);
            NsP[jB * 2 + 1] = make_float2(nvB[2], nvB[3]);
        }
        __syncwarp();
        NsP[tid * 2]     = make_float2(nvA[0], nvA[1]);
        NsP[tid * 2 + 1] = make_float2(nvA[2], nvA[3]);
    }
    __syncthreads();

    // ========== Phase 4: P = node @ W1^T (d-sixths x o-quads, 150 thr) =====
    ull acc4[4][2];
#pragma unroll
    for (int j = 0; j < 4; j++) { acc4[j][0] = 0; acc4[j][1] = 0; }
    const ulonglong2* NsV = reinterpret_cast<const ulonglong2*>(NsP);
    if (tid < 150) {
        const int seg = tid / 25, og = tid % 25;
        const int d0 = seg * 50, o0 = og * 4;
#pragma unroll 5
        for (int u = 0; u < 25; u++) {
            int d = d0 + 2 * u;
            float4 wa  = *reinterpret_cast<const float4*>(g_W1t + (size_t)d * 100 + o0);
            float4 wb2 = *reinterpret_cast<const float4*>(g_W1t + (size_t)(d + 1) * 100 + o0);
            ulonglong2 N0 = NsV[d], N1 = NsV[d + 1];
            fma2p(acc4[0], wa.x,  N0.x, N0.y);
            fma2p(acc4[1], wa.y,  N0.x, N0.y);
            fma2p(acc4[2], wa.z,  N0.x, N0.y);
            fma2p(acc4[3], wa.w,  N0.x, N0.y);
            fma2p(acc4[0], wb2.x, N1.x, N1.y);
            fma2p(acc4[1], wb2.y, N1.x, N1.y);
            fma2p(acc4[2], wb2.z, N1.x, N1.y);
            fma2p(acc4[3], wb2.w, N1.x, N1.y);
        }
        if (seg) {
            ull* g = GH + (size_t)((seg - 1) * 25 + og) * 8;
#pragma unroll
            for (int j = 0; j < 4; j++) { g[j * 2] = acc4[j][0]; g[j * 2 + 1] = acc4[j][1]; }
        }
    }
    __syncthreads();
    if (tid < 25) {
#pragma unroll
        for (int s = 0; s < 5; s++) {
            const ull* g = GH + (size_t)(s * 25 + tid) * 8;
#pragma unroll
            for (int j = 0; j < 4; j++) {
                acc4[j][0] = f2add(acc4[j][0], g[j * 2]);
                acc4[j][1] = f2add(acc4[j][1], g[j * 2 + 1]);
            }
        }
#pragma unroll
        for (int jj = 0; jj < 4; jj++) {
            int o = tid * 4 + jj, e = o >> 1;
            float* dst = ((o & 1) ? g_Pb : g_Pa) + (size_t)(b * SS + s0) * DEPC + e;
#pragma unroll
            for (int rp = 0; rp < 2; rp++) {
                float f0, f1;
                upk2(acc4[jj][rp], f0, f1);
                dst[(2 * rp) * DEPC]     = f0;
                dst[(2 * rp + 1) * DEPC] = f1;
            }
        }
    }
}

// =======================================================================
// k_edge: edge[b,i,j,e] = pa[b,j,e] + pb[b,i,e] + W1_b[e]
// =======================================================================
__global__ __launch_bounds__(800) void k_edge(const float* __restrict__ W1b,
                                              float* __restrict__ edge) {
    const int bi0 = blockIdx.x * 2;
    const int b   = bi0 >> 7;
    const int tid = threadIdx.x;
    const int e2  = tid % 25;
    const int j0  = tid / 25;

    float2 w = reinterpret_cast<const float2*>(W1b)[e2];
    const ull* pa = reinterpret_cast<const ull*>(g_Pa + (size_t)b * SS * DEPC);
    ull pav[4];
#pragma unroll
    for (int k = 0; k < 4; k++) pav[k] = pa[(j0 + 32 * k) * 25 + e2];

#pragma unroll
    for (int r = 0; r < 2; r++) {
        int bi = bi0 + r;
        float2 pv = reinterpret_cast<const float2*>(g_Pb + (size_t)bi * DEPC)[e2];
        ull pr = pk2(pv.x + w.x, pv.y + w.y);
        ull* out = reinterpret_cast<ull*>(edge + (size_t)bi * SS * DEPC);
#pragma unroll
        for (int k = 0; k < 4; k++) out[(j0 + 32 * k) * 25 + e2] = f2add(pav[k], pr);
    }
}

// =======================================================================
extern "C" void kernel_launch(void* const* d_in, const int* in_sizes, int n_in,
                              void* d_out, int out_size) {
    const float* wps = (const float*)d_in[0];
    /* d_in[1] = weight_adj (int64) — unused */
    const float* x   = (const float*)d_in[2];
    const float* sl  = (const float*)d_in[3];
    const float* Ww  = (const float*)d_in[4];
    const float* Wb  = (const float*)d_in[5];
    const float* lna = (const float*)d_in[6];
    const float* lnb = (const float*)d_in[7];
    const float* W1w = (const float*)d_in[8];
    const float* W1b = (const float*)d_in[9];

    float* out  = (float*)d_out;
    float* node = out;
    float* edge = out + BB * SS * DD;

    cudaFuncSetAttribute((const void*)k_fused,
                         cudaFuncAttributeMaxDynamicSharedMemorySize, SMEM_BYTES);

    k_prep <<<270, 256>>>(Ww, W1w, x);
    k_fused<<<BB * (SS / RROWS), NTHR, SMEM_BYTES>>>(wps, sl, x, Wb, lna, lnb, node);
    k_edge <<<BB * SS / 2, 800>>>(W1b, edge);
}